// round 6
// baseline (speedup 1.0000x reference)
#include <cuda_runtime.h>

static constexpr int C = 512;
static constexpr int B = 8;
static constexpr int L = 4096;
static constexpr int TOPK = 256;          // C * (1 - EXCHANGE_RATIO)
static constexpr int L4 = L / 4;          // 1024 float4 per channel row

// Per-array tables (written by blocks 0/1 of the fused kernel):
//   g_tp[a][c] = -1 if channel c is in top-k of |bn_a|, else its position in
//                the ascending-index list of non-top channels (0..255).
//   g_nt[a][k] = k-th non-top channel of array a (ascending index order).
__device__ int g_tp[2][C];
__device__ int g_nt[2][TOPK];
// Handshake state (zero-initialized; reset by the last block each run).
__device__ int g_ready;
__device__ int g_done;

__global__ void __launch_bounds__(256)
exchange_fused_kernel(const float4* __restrict__ x1,
                      const float4* __restrict__ x2,
                      float4* __restrict__ out,
                      const float* __restrict__ bn1,
                      const float* __restrict__ bn2) {
    unsigned row = blockIdx.x;             // which*4096 + b*512 + c
    int t = threadIdx.x;

    // ─── Phase 1: blocks 0 and 1 build the map for bn1 / bn2 ───
    if (row < 2) {
        __shared__ unsigned long long key[C];
        __shared__ unsigned ballots[16];

        int a = row;
        const float* bn = a ? bn2 : bn1;

        // Non-negative floats order like their bit patterns.
        // key = (bits << 10) | (1023 - c): on equal values the smaller index
        // ranks higher, matching jax.lax.top_k tie semantics.
        {
            unsigned b0 = __float_as_uint(fabsf(bn[t]));
            unsigned b1 = __float_as_uint(fabsf(bn[t + 256]));
            key[t]       = ((unsigned long long)b0 << 10) | (unsigned)(1023 - t);
            key[t + 256] = ((unsigned long long)b1 << 10) | (unsigned)(1023 - (t + 256));
        }
        __syncthreads();

        // Each thread ranks two channels: c0 = t, c1 = t + 256.
        // One LDS.128 per iteration serves both channels' compares.
        unsigned long long k0 = key[t], k1 = key[t + 256];
        int r0 = 0, r1 = 0;
        const ulonglong2* k2 = (const ulonglong2*)key;
        #pragma unroll 8
        for (int j = 0; j < C / 2; ++j) {
            ulonglong2 v = k2[j];
            r0 += (v.x > k0) + (v.y > k0);
            r1 += (v.x > k1) + (v.y > k1);
        }
        bool nt0 = (r0 >= TOPK);
        bool nt1 = (r1 >= TOPK);

        // Ballot scan over all 512 channels: warps 0-7 cover c=t (0..255),
        // slots 8-15 cover c=t+256 (256..511).
        unsigned bal0 = __ballot_sync(0xFFFFFFFFu, nt0);
        unsigned bal1 = __ballot_sync(0xFFFFFFFFu, nt1);
        int warp = t >> 5, lane = t & 31;
        if (lane == 0) { ballots[warp] = bal0; ballots[8 + warp] = bal1; }
        __syncthreads();

        int pre0 = 0, pre1 = 0;
        #pragma unroll
        for (int w = 0; w < 16; ++w) {
            unsigned m = ballots[w];
            if (w < warp)     pre0 += __popc(m);
            if (w < 8 + warp) pre1 += __popc(m);
        }
        unsigned lt = (1u << lane) - 1u;
        int p0 = pre0 + __popc(bal0 & lt);
        int p1 = pre1 + __popc(bal1 & lt);

        if (nt0) g_nt[a][p0] = t;
        if (nt1) g_nt[a][p1] = t + 256;
        g_tp[a][t]       = nt0 ? p0 : -1;
        g_tp[a][t + 256] = nt1 ? p1 : -1;

        __syncthreads();
        if (t == 0) {
            __threadfence();               // publish tables before flag
            atomicAdd(&g_ready, 1);
        }
    }

    // ─── Phase 2: wait for both tables, then copy this row ───
    if (t == 0) {
        while (*(volatile int*)&g_ready != 2) __nanosleep(100);
        __threadfence();                   // acquire
    }
    __syncthreads();

    unsigned c     = row & (C - 1);
    unsigned wb    = row >> 9;
    unsigned which = wb >> 3;
    unsigned b     = wb & (B - 1);

    // y_{which}[:,c,:] keeps x_{which} if c is top in bn_{which}, else takes
    // x_{other}[:, nt_other[pos_which(c)], :].
    int tp = g_tp[which][c];
    unsigned o = which ^ 1u;
    int s = (tp < 0) ? (int)((which << 9) | c)
                     : (int)((o << 9) | (unsigned)g_nt[o][tp]);

    const float4* __restrict__ src = (s & 512) ? x2 : x1;
    unsigned sbase = (((b << 9) + (unsigned)(s & 511)) << 10) + (unsigned)t;
    unsigned dbase = (row << 10) + (unsigned)t;

    float4 v0 = __ldcs(src + sbase);
    float4 v1 = __ldcs(src + sbase + 256);
    float4 v2 = __ldcs(src + sbase + 512);
    float4 v3 = __ldcs(src + sbase + 768);
    __stcs(out + dbase,       v0);
    __stcs(out + dbase + 256, v1);
    __stcs(out + dbase + 512, v2);
    __stcs(out + dbase + 768, v3);

    // ─── Reset handshake for the next graph replay (last block only) ───
    if (t == 0) {
        int d = atomicAdd(&g_done, 1);
        if (d == (int)gridDim.x - 1) {
            g_done = 0;
            g_ready = 0;
        }
    }
}

extern "C" void kernel_launch(void* const* d_in, const int* in_sizes, int n_in,
                              void* d_out, int out_size) {
    const float* x1  = (const float*)d_in[0];
    const float* x2  = (const float*)d_in[1];
    const float* bn1 = (const float*)d_in[2];
    const float* bn2 = (const float*)d_in[3];

    const unsigned rows = 2u * B * C;      // 8192 channel rows
    exchange_fused_kernel<<<rows, 256>>>((const float4*)x1,
                                         (const float4*)x2,
                                         (float4*)d_out,
                                         bn1, bn2);
}

// round 7
// speedup vs baseline: 1.0487x; 1.0487x over previous
#include <cuda_runtime.h>

static constexpr int C = 512;
static constexpr int B = 8;
static constexpr int L = 4096;
static constexpr int TOPK = 256;          // C * (1 - EXCHANGE_RATIO)
static constexpr int L4 = L / 4;          // 1024 float4 per channel row

// Per-array tables (written by blocks 0/1):
//   g_tp[a][c] = -1 if channel c is in top-k of |bn_a|, else its position in
//                the ascending-index list of non-top channels (0..255).
//   g_nt[a][k] = k-th non-top channel of array a (ascending index order).
__device__ int g_tp[2][C];
__device__ int g_nt[2][TOPK];
// Handshake state (zero-initialized; reset by the last block each run).
__device__ int g_ready;
__device__ int g_done;

__global__ void __launch_bounds__(256)
exchange_fused_kernel(const float4* __restrict__ x1,
                      const float4* __restrict__ x2,
                      float4* __restrict__ out,
                      const float* __restrict__ bn1,
                      const float* __restrict__ bn2) {
    unsigned row = blockIdx.x;             // INPUT row: a*4096 + b*512 + c
    int t = threadIdx.x;

    // ─── Phase 1: blocks 0 and 1 build the map for bn1 / bn2 ───
    if (row < 2) {
        __shared__ unsigned long long key[C];
        __shared__ unsigned ballots[16];

        int a = row;
        const float* bn = a ? bn2 : bn1;

        // Non-negative floats order like their bit patterns.
        // key = (bits << 10) | (1023 - c): equal values -> smaller index
        // ranks higher, matching jax.lax.top_k tie semantics.
        {
            unsigned b0 = __float_as_uint(fabsf(bn[t]));
            unsigned b1 = __float_as_uint(fabsf(bn[t + 256]));
            key[t]       = ((unsigned long long)b0 << 10) | (unsigned)(1023 - t);
            key[t + 256] = ((unsigned long long)b1 << 10) | (unsigned)(1023 - (t + 256));
        }
        __syncthreads();

        // Each thread ranks two channels; one LDS.128/iter serves both.
        unsigned long long k0 = key[t], k1 = key[t + 256];
        int r0 = 0, r1 = 0;
        const ulonglong2* k2 = (const ulonglong2*)key;
        #pragma unroll 8
        for (int j = 0; j < C / 2; ++j) {
            ulonglong2 v = k2[j];
            r0 += (v.x > k0) + (v.y > k0);
            r1 += (v.x > k1) + (v.y > k1);
        }
        bool nt0 = (r0 >= TOPK);
        bool nt1 = (r1 >= TOPK);

        // Ballot scan: slots 0-7 cover c = t (0..255), 8-15 cover c = t+256.
        unsigned bal0 = __ballot_sync(0xFFFFFFFFu, nt0);
        unsigned bal1 = __ballot_sync(0xFFFFFFFFu, nt1);
        int warp = t >> 5, lane = t & 31;
        if (lane == 0) { ballots[warp] = bal0; ballots[8 + warp] = bal1; }
        __syncthreads();

        int pre0 = 0, pre1 = 0;
        #pragma unroll
        for (int w = 0; w < 16; ++w) {
            unsigned m = ballots[w];
            if (w < warp)     pre0 += __popc(m);
            if (w < 8 + warp) pre1 += __popc(m);
        }
        unsigned lt = (1u << lane) - 1u;
        int p0 = pre0 + __popc(bal0 & lt);
        int p1 = pre1 + __popc(bal1 & lt);

        if (nt0) g_nt[a][p0] = t;
        if (nt1) g_nt[a][p1] = t + 256;
        g_tp[a][t]       = nt0 ? p0 : -1;
        g_tp[a][t + 256] = nt1 ? p1 : -1;

        __syncthreads();
        if (t == 0) {
            __threadfence();               // publish tables before flag
            atomicAdd(&g_ready, 1);
        }
    }

    // ─── Phase 2: source-stationary copy ───
    // Load address is map-independent: issue loads FIRST so the DRAM fetch
    // overlaps the map computation / flag spin.
    unsigned c  = row & (C - 1);
    unsigned ab = row >> 9;
    unsigned a  = ab >> 3;                 // source array
    unsigned b  = ab & (B - 1);

    const float4* __restrict__ src = a ? x2 : x1;
    unsigned sbase = (((b << 9) + c) << 10) + (unsigned)t;

    float4 v0 = __ldcs(src + sbase);
    float4 v1 = __ldcs(src + sbase + 256);
    float4 v2 = __ldcs(src + sbase + 512);
    float4 v3 = __ldcs(src + sbase + 768);

    // Wait for both tables (loads are in flight meanwhile).
    if (t == 0) {
        while (*(volatile int*)&g_ready != 2) __nanosleep(64);
        __threadfence();                   // acquire
    }
    __syncthreads();

    // Destination: x_a[:,c,:] -> y_a[:,c,:] if c is top in bn_a,
    // else -> y_{a^1}[:, nt_{a^1}[pos_a(c)], :] (order-aligned exchange).
    int tp = g_tp[a][c];
    unsigned dw, dc;
    if (tp < 0) { dw = a;      dc = c; }
    else        { dw = a ^ 1u; dc = (unsigned)g_nt[a ^ 1u][tp]; }
    unsigned drow  = (((dw << 3) + b) << 9) + dc;
    unsigned dbase = (drow << 10) + (unsigned)t;

    __stcs(out + dbase,       v0);
    __stcs(out + dbase + 256, v1);
    __stcs(out + dbase + 512, v2);
    __stcs(out + dbase + 768, v3);

    // ─── Reset handshake for the next graph replay (last block only) ───
    if (t == 0) {
        int d = atomicAdd(&g_done, 1);
        if (d == (int)gridDim.x - 1) {
            g_done = 0;
            g_ready = 0;
        }
    }
}

extern "C" void kernel_launch(void* const* d_in, const int* in_sizes, int n_in,
                              void* d_out, int out_size) {
    const float* x1  = (const float*)d_in[0];
    const float* x2  = (const float*)d_in[1];
    const float* bn1 = (const float*)d_in[2];
    const float* bn2 = (const float*)d_in[3];

    const unsigned rows = 2u * B * C;      // 8192 input channel rows
    exchange_fused_kernel<<<rows, 256>>>((const float4*)x1,
                                         (const float4*)x2,
                                         (float4*)d_out,
                                         bn1, bn2);
}